// round 8
// baseline (speedup 1.0000x reference)
#include <cuda_runtime.h>
#include <cuda_bf16.h>

// Problem constants (from reference: N=100000, F=128, Fo=64, E=1600000)
#define NMAX 100000
#define FDIM 128
#define FO   64

__device__ __align__(16) float g_deg[NMAX];
__device__ __align__(16) float g_hs [NMAX * FO];   // h[i] * dinv[i]
__device__ __align__(16) float g_tmp[NMAX * FO];   // aggregate (init = hs -> self loop)

// ---- packed f32x2 helpers (sm_103a) ---------------------------------------
__device__ __forceinline__ unsigned long long pk2(float s) {
    unsigned long long r;
    asm("mov.b64 %0, {%1, %1};" : "=l"(r) : "f"(s));
    return r;
}
__device__ __forceinline__ void fma2(unsigned long long& d,
                                     unsigned long long a,
                                     unsigned long long b) {
    asm("fma.rn.f32x2 %0, %1, %2, %0;" : "+l"(d) : "l"(a), "l"(b));
}
__device__ __forceinline__ float2 unpk2(unsigned long long v) {
    float2 f;
    asm("mov.b64 {%0, %1}, %2;" : "=f"(f.x), "=f"(f.y) : "l"(v));
    return f;
}

// ---------------------------------------------------------------------------
__global__ void k_deg_init(int N) {
    int i = blockIdx.x * blockDim.x + threadIdx.x;
    if (i < N) g_deg[i] = 1.0f;
}

__global__ void k_deg_acc(const int* __restrict__ ei, int E) {
    int t = blockIdx.x * blockDim.x + threadIdx.x;
    int e0 = t * 4;
    if (e0 + 3 < E) {
        int4 d = *(const int4*)(ei + E + e0);
        atomicAdd(&g_deg[d.x], 1.0f);
        atomicAdd(&g_deg[d.y], 1.0f);
        atomicAdd(&g_deg[d.z], 1.0f);
        atomicAdd(&g_deg[d.w], 1.0f);
    } else {
        for (int e = e0; e < E; e++) atomicAdd(&g_deg[ei[E + e]], 1.0f);
    }
}

// ---------------------------------------------------------------------------
// K2: hs = (x @ W^T) * dinv ; tmp = hs (self-loop init)
// 256 threads, 128 rows/block. Thread = 4 rows x 8 cols (16 f32x2 accs).
// Same 96KB tile as R6 but 2x the warps (16/SM) for latency hiding.
#define GROWS 128

// x swizzle: 16B-granular rotation; thread's 4 rows stay contiguous (LDS.128).
#define XGRP(k, g)  ((((g) + (k)) & 31) * 4)

__global__ __launch_bounds__(256) void k_gemm(const float* __restrict__ x,
                                              const float* __restrict__ W,
                                              int N) {
    extern __shared__ float smem[];
    float* W_sh = smem;                 // [k*64 + c] = W[c*128 + k]   (32KB)
    float* x_sh = smem + FDIM * FO;     // [k*128 + swizzle(r)]        (64KB)

    int tid = threadIdx.x;
    int row0 = blockIdx.x * GROWS;

    // load W transposed (k-major)
    #pragma unroll
    for (int i = tid; i < FO * FDIM; i += 256) {
        int c = i >> 7;
        int k = i & 127;
        W_sh[k * FO + c] = W[i];
    }

    // load x rows: coalesced global read, swizzled k-major smem store
    #pragma unroll
    for (int i = tid; i < GROWS * FDIM; i += 256) {
        int r = i >> 7;        // 0..127
        int k = i & 127;
        int gr = row0 + r;
        float v = (gr < N) ? x[(long)gr * FDIM + k] : 0.0f;
        x_sh[k * GROWS + XGRP(k, r >> 2) + (r & 3)] = v;
    }
    __syncthreads();

    int rg = tid >> 3;          // 0..31 -> rows rg*4 .. rg*4+3
    int c0 = (tid & 7) << 3;    // 0,8,...,56

    unsigned long long acc[4][4];
    #pragma unroll
    for (int i = 0; i < 4; i++)
        #pragma unroll
        for (int j = 0; j < 4; j++) acc[i][j] = 0ull;

    #pragma unroll 8
    for (int k = 0; k < FDIM; k++) {
        float4 xa = *(const float4*)&x_sh[k * GROWS + XGRP(k, rg)];
        ulonglong2 w01 = *(const ulonglong2*)&W_sh[k * FO + c0];
        ulonglong2 w23 = *(const ulonglong2*)&W_sh[k * FO + c0 + 4];
        float xs[4] = {xa.x, xa.y, xa.z, xa.w};
        #pragma unroll
        for (int i = 0; i < 4; i++) {
            unsigned long long p = pk2(xs[i]);
            fma2(acc[i][0], p, w01.x);
            fma2(acc[i][1], p, w01.y);
            fma2(acc[i][2], p, w23.x);
            fma2(acc[i][3], p, w23.y);
        }
    }

    #pragma unroll
    for (int i = 0; i < 4; i++) {
        int gr = row0 + rg * 4 + i;
        if (gr >= N) continue;
        float dinv = rsqrtf(g_deg[gr]);
        float2 p0 = unpk2(acc[i][0]), p1 = unpk2(acc[i][1]);
        float2 p2 = unpk2(acc[i][2]), p3 = unpk2(acc[i][3]);
        float4 v0 = make_float4(p0.x * dinv, p0.y * dinv, p1.x * dinv, p1.y * dinv);
        float4 v1 = make_float4(p2.x * dinv, p2.y * dinv, p3.x * dinv, p3.y * dinv);
        long base = (long)gr * FO + c0;
        *(float4*)&g_hs [base]     = v0;
        *(float4*)&g_hs [base + 4] = v1;
        *(float4*)&g_tmp[base]     = v0;
        *(float4*)&g_tmp[base + 4] = v1;
    }
}

// ---------------------------------------------------------------------------
// K3: scatter-add: tmp[dst] += hs[src]  — warp per edge, float2 lanes.
__global__ __launch_bounds__(256) void k_scatter(const int* __restrict__ ei, int E) {
    int warp = (int)((blockIdx.x * blockDim.x + threadIdx.x) >> 5);
    int lane = threadIdx.x & 31;
    int e0 = warp << 5;
    if (e0 >= E) return;
    int n = E - e0; if (n > 32) n = 32;

    int mysrc = 0, mydst = 0;
    if (lane < n) {
        mysrc = __ldg(ei + e0 + lane);
        mydst = __ldg(ei + E + e0 + lane);
    }

    int j = lane << 1;   // 0,2,...,62
    #pragma unroll 4
    for (int i = 0; i < n; i++) {
        int src = __shfl_sync(0xFFFFFFFFu, mysrc, i);
        int dst = __shfl_sync(0xFFFFFFFFu, mydst, i);
        float2 v = __ldg((const float2*)(g_hs + (long)src * FO + j));
        float* p = g_tmp + (long)dst * FO + j;
        asm volatile("red.global.add.v2.f32 [%0], {%1, %2};"
                     :: "l"(p), "f"(v.x), "f"(v.y) : "memory");
    }
}

// ---------------------------------------------------------------------------
// K4: out = sigmoid( relu(dinv*tmp + b_conv) . W_lin + b_lin )  — warp per node
__global__ void k_final(const float* __restrict__ Wl,
                        const float* __restrict__ bl,
                        const float* __restrict__ bconv,
                        float* __restrict__ out, int N) {
    int warp = (int)((blockIdx.x * blockDim.x + threadIdx.x) >> 5);
    int lane = threadIdx.x & 31;
    if (warp >= N) return;

    float dinv = rsqrtf(g_deg[warp]);
    float2 tv = *(const float2*)&g_tmp[(long)warp * FO + lane * 2];
    float2 wv = *(const float2*)&Wl[lane * 2];
    float2 bc = *(const float2*)&bconv[lane * 2];

    float v0 = fmaxf(fmaf(tv.x, dinv, bc.x), 0.0f);
    float v1 = fmaxf(fmaf(tv.y, dinv, bc.y), 0.0f);
    float s  = v0 * wv.x + v1 * wv.y;

    #pragma unroll
    for (int o = 16; o; o >>= 1) s += __shfl_xor_sync(0xFFFFFFFFu, s, o);

    if (lane == 0) {
        float z = s + bl[0];
        out[warp] = 1.0f / (1.0f + expf(-z));
    }
}

// ---------------------------------------------------------------------------
extern "C" void kernel_launch(void* const* d_in, const int* in_sizes, int n_in,
                              void* d_out, int out_size) {
    const float* x     = (const float*)d_in[0];
    const int*   ei    = (const int*)  d_in[1];
    const float* Wc    = (const float*)d_in[2];
    const float* bc    = (const float*)d_in[3];
    const float* Wl    = (const float*)d_in[4];
    const float* bl    = (const float*)d_in[5];
    float*       out   = (float*)d_out;

    int N = in_sizes[0] / FDIM;
    int E = in_sizes[1] / 2;
    if (N > NMAX) N = NMAX;

    const int GEMM_SMEM = (FDIM * FO + GROWS * FDIM) * (int)sizeof(float); // 96KB
    cudaFuncSetAttribute(k_gemm, cudaFuncAttributeMaxDynamicSharedMemorySize,
                         GEMM_SMEM);

    k_deg_init<<<(N + 255) / 256, 256>>>(N);
    k_deg_acc <<<((E + 3) / 4 + 255) / 256, 256>>>(ei, E);
    k_gemm    <<<(N + GROWS - 1) / GROWS, 256, GEMM_SMEM>>>(x, Wc, N);
    {
        int nwarp  = (E + 31) / 32;
        int blocks = (nwarp + 7) / 8;
        k_scatter<<<blocks, 256>>>(ei, E);
    }
    k_final<<<(N + 7) / 8, 256>>>(Wl, bl, bc, out, N);
}

// round 9
// speedup vs baseline: 1.1161x; 1.1161x over previous
#include <cuda_runtime.h>
#include <cuda_fp16.h>
#include <cuda_bf16.h>

// Problem constants (from reference: N=100000, F=128, Fo=64, E=1600000)
#define NMAX 100000
#define FDIM 128
#define FO   64

__device__ __align__(16) float  g_deg[NMAX];
__device__ __align__(16) __half g_hs [NMAX * FO];  // fp16 messages: h[i]*dinv[i]
__device__ __align__(16) float  g_tmp[NMAX * FO];  // fp32 aggregate (init = exact self loop)

// ---- packed f32x2 helpers (sm_103a) ---------------------------------------
__device__ __forceinline__ unsigned long long pk2(float s) {
    unsigned long long r;
    asm("mov.b64 %0, {%1, %1};" : "=l"(r) : "f"(s));
    return r;
}
__device__ __forceinline__ void fma2(unsigned long long& d,
                                     unsigned long long a,
                                     unsigned long long b) {
    asm("fma.rn.f32x2 %0, %1, %2, %0;" : "+l"(d) : "l"(a), "l"(b));
}
__device__ __forceinline__ float2 unpk2(unsigned long long v) {
    float2 f;
    asm("mov.b64 {%0, %1}, %2;" : "=f"(f.x), "=f"(f.y) : "l"(v));
    return f;
}

// ---------------------------------------------------------------------------
__global__ void k_deg_init(int N) {
    int i = blockIdx.x * blockDim.x + threadIdx.x;
    if (i < N) g_deg[i] = 1.0f;
}

__global__ void k_deg_acc(const int* __restrict__ ei, int E) {
    int t = blockIdx.x * blockDim.x + threadIdx.x;
    int e0 = t * 4;
    if (e0 + 3 < E) {
        int4 d = *(const int4*)(ei + E + e0);
        atomicAdd(&g_deg[d.x], 1.0f);
        atomicAdd(&g_deg[d.y], 1.0f);
        atomicAdd(&g_deg[d.z], 1.0f);
        atomicAdd(&g_deg[d.w], 1.0f);
    } else {
        for (int e = e0; e < E; e++) atomicAdd(&g_deg[ei[E + e]], 1.0f);
    }
}

// ---------------------------------------------------------------------------
// K2: hs(fp16) = (x @ W^T) * dinv ; tmp(fp32) = same (exact self-loop init)
// R7 config (best measured): 128 threads, 128 rows/block, thread = 8x8.
#define GROWS 128
#define XGRP(k, g)  ((((g) + (k)) & 31) * 4)

__global__ __launch_bounds__(128) void k_gemm(const float* __restrict__ x,
                                              const float* __restrict__ W,
                                              int N) {
    extern __shared__ float smem[];
    float* W_sh = smem;                 // [k*64 + c] = W[c*128 + k]   (32KB)
    float* x_sh = smem + FDIM * FO;     // [k*128 + swizzle(r)]        (64KB)

    int tid = threadIdx.x;
    int row0 = blockIdx.x * GROWS;

    #pragma unroll
    for (int i = tid; i < FO * FDIM; i += 128) {
        int c = i >> 7;
        int k = i & 127;
        W_sh[k * FO + c] = W[i];
    }

    #pragma unroll
    for (int i = tid; i < GROWS * FDIM; i += 128) {
        int r = i >> 7;
        int k = i & 127;
        int gr = row0 + r;
        float v = (gr < N) ? x[(long)gr * FDIM + k] : 0.0f;
        x_sh[k * GROWS + XGRP(k, r >> 2) + (r & 3)] = v;
    }
    __syncthreads();

    int rg = tid >> 3;          // 0..15 -> rows rg*8 .. rg*8+7
    int c0 = (tid & 7) << 3;    // 0,8,...,56

    unsigned long long acc[8][4];
    #pragma unroll
    for (int i = 0; i < 8; i++)
        #pragma unroll
        for (int j = 0; j < 4; j++) acc[i][j] = 0ull;

    #pragma unroll 4
    for (int k = 0; k < FDIM; k++) {
        float4 xa = *(const float4*)&x_sh[k * GROWS + XGRP(k, rg * 2)];
        float4 xb = *(const float4*)&x_sh[k * GROWS + XGRP(k, rg * 2 + 1)];
        ulonglong2 w01 = *(const ulonglong2*)&W_sh[k * FO + c0];
        ulonglong2 w23 = *(const ulonglong2*)&W_sh[k * FO + c0 + 4];
        float xs[8] = {xa.x, xa.y, xa.z, xa.w, xb.x, xb.y, xb.z, xb.w};
        #pragma unroll
        for (int i = 0; i < 8; i++) {
            unsigned long long p = pk2(xs[i]);
            fma2(acc[i][0], p, w01.x);
            fma2(acc[i][1], p, w01.y);
            fma2(acc[i][2], p, w23.x);
            fma2(acc[i][3], p, w23.y);
        }
    }

    #pragma unroll
    for (int i = 0; i < 8; i++) {
        int gr = row0 + rg * 8 + i;
        if (gr >= N) continue;
        float dinv = rsqrtf(g_deg[gr]);
        float2 p0 = unpk2(acc[i][0]), p1 = unpk2(acc[i][1]);
        float2 p2 = unpk2(acc[i][2]), p3 = unpk2(acc[i][3]);
        float4 v0 = make_float4(p0.x * dinv, p0.y * dinv, p1.x * dinv, p1.y * dinv);
        float4 v1 = make_float4(p2.x * dinv, p2.y * dinv, p3.x * dinv, p3.y * dinv);
        long base = (long)gr * FO + c0;
        // exact fp32 self-loop contribution
        *(float4*)&g_tmp[base]     = v0;
        *(float4*)&g_tmp[base + 4] = v1;
        // fp16 message copy (8 halves = 16B)
        __half2 hh[4];
        hh[0] = __floats2half2_rn(v0.x, v0.y);
        hh[1] = __floats2half2_rn(v0.z, v0.w);
        hh[2] = __floats2half2_rn(v1.x, v1.y);
        hh[3] = __floats2half2_rn(v1.z, v1.w);
        *(uint4*)&g_hs[base] = *(const uint4*)hh;
    }
}

// ---------------------------------------------------------------------------
// K3: scatter-add: tmp[dst] += hs[src]  — warp per edge.
// Gather: one LDG.32 of half2 per edge (32 lanes x 4B = ONE 128B line).
// Accumulate: fp32 RED.v2 (2 lines). LTS bytes/edge: 384 vs 512 before.
__global__ __launch_bounds__(256) void k_scatter(const int* __restrict__ ei, int E) {
    int warp = (int)((blockIdx.x * blockDim.x + threadIdx.x) >> 5);
    int lane = threadIdx.x & 31;
    int e0 = warp << 5;
    if (e0 >= E) return;
    int n = E - e0; if (n > 32) n = 32;

    int mysrc = 0, mydst = 0;
    if (lane < n) {
        mysrc = __ldg(ei + e0 + lane);
        mydst = __ldg(ei + E + e0 + lane);
    }

    int j = lane << 1;   // half/float index 0,2,...,62
    #pragma unroll 4
    for (int i = 0; i < n; i++) {
        int src = __shfl_sync(0xFFFFFFFFu, mysrc, i);
        int dst = __shfl_sync(0xFFFFFFFFu, mydst, i);
        __half2 hv = __ldg((const __half2*)(g_hs + (long)src * FO) + lane);
        float2 v = __half22float2(hv);
        float* p = g_tmp + (long)dst * FO + j;
        asm volatile("red.global.add.v2.f32 [%0], {%1, %2};"
                     :: "l"(p), "f"(v.x), "f"(v.y) : "memory");
    }
}

// ---------------------------------------------------------------------------
// K4: out = sigmoid( relu(dinv*tmp + b_conv) . W_lin + b_lin )  — warp per node
__global__ void k_final(const float* __restrict__ Wl,
                        const float* __restrict__ bl,
                        const float* __restrict__ bconv,
                        float* __restrict__ out, int N) {
    int warp = (int)((blockIdx.x * blockDim.x + threadIdx.x) >> 5);
    int lane = threadIdx.x & 31;
    if (warp >= N) return;

    float dinv = rsqrtf(g_deg[warp]);
    float2 tv = *(const float2*)&g_tmp[(long)warp * FO + lane * 2];
    float2 wv = *(const float2*)&Wl[lane * 2];
    float2 bc = *(const float2*)&bconv[lane * 2];

    float v0 = fmaxf(fmaf(tv.x, dinv, bc.x), 0.0f);
    float v1 = fmaxf(fmaf(tv.y, dinv, bc.y), 0.0f);
    float s  = v0 * wv.x + v1 * wv.y;

    #pragma unroll
    for (int o = 16; o; o >>= 1) s += __shfl_xor_sync(0xFFFFFFFFu, s, o);

    if (lane == 0) {
        float z = s + bl[0];
        out[warp] = 1.0f / (1.0f + expf(-z));
    }
}

// ---------------------------------------------------------------------------
extern "C" void kernel_launch(void* const* d_in, const int* in_sizes, int n_in,
                              void* d_out, int out_size) {
    const float* x     = (const float*)d_in[0];
    const int*   ei    = (const int*)  d_in[1];
    const float* Wc    = (const float*)d_in[2];
    const float* bc    = (const float*)d_in[3];
    const float* Wl    = (const float*)d_in[4];
    const float* bl    = (const float*)d_in[5];
    float*       out   = (float*)d_out;

    int N = in_sizes[0] / FDIM;
    int E = in_sizes[1] / 2;
    if (N > NMAX) N = NMAX;

    const int GEMM_SMEM = (FDIM * FO + GROWS * FDIM) * (int)sizeof(float); // 96KB
    cudaFuncSetAttribute(k_gemm, cudaFuncAttributeMaxDynamicSharedMemorySize,
                         GEMM_SMEM);

    k_deg_init<<<(N + 255) / 256, 256>>>(N);
    k_deg_acc <<<((E + 3) / 4 + 255) / 256, 256>>>(ei, E);
    k_gemm    <<<(N + GROWS - 1) / GROWS, 128, GEMM_SMEM>>>(x, Wc, N);
    {
        int nwarp  = (E + 31) / 32;
        int blocks = (nwarp + 7) / 8;
        k_scatter<<<blocks, 256>>>(ei, E);
    }
    k_final<<<(N + 7) / 8, 256>>>(Wl, bl, bc, out, N);
}